// round 15
// baseline (speedup 1.0000x reference)
#include <cuda_runtime.h>
#include <cuda_bf16.h>
#include <cuda_fp16.h>
#include <cstdint>
#include <math.h>

#define DM   1024
#define NH   16
#define HD   64
#define SEQ  2048
#define NB   4
#define MTOT (NB * SEQ)   // 8192

// ---------------- global scratch: layouts match smem staging ----------------
#define QKV_ROW 72                         // fp16 elements per padded row (144B)
__device__ __half g_qh[(size_t)NB * NH * SEQ * QKV_ROW];   // Q single fp16
__device__ __half g_kh[(size_t)NB * NH * SEQ * QKV_ROW];   // K single fp16
__device__ __half g_vh[(size_t)NB * NH * SEQ * QKV_ROW];   // V single fp16

#define ABT ((size_t)32 * MTOT * 80)       // one activation tensor, k-blocked
#define WBT ((size_t)32 * DM * 80)         // one weight tensor, k-blocked
__device__ char g_ah[3 * ABT];             // activations single fp16
__device__ char g_wh[4 * WBT];             // weights hi
__device__ char g_wl[4 * WBT];             // weights lo
__device__ char g_aoh[ABT];                // attn-out single fp16, k-blocked

// ============================ helpers =======================================
__device__ __forceinline__ uint32_t smem_u32(const void* p) {
    uint32_t a;
    asm("{ .reg .u64 t; cvta.to.shared.u64 t, %1; cvt.u32.u64 %0, t; }"
        : "=r"(a) : "l"(p));
    return a;
}
#define MBARRIER_INIT(a, c) \
    asm volatile("mbarrier.init.shared.b64 [%0], %1;" :: "r"((uint32_t)(a)), "r"((uint32_t)(c)) : "memory")
#define MBARRIER_EXPECT_TX(a, b) \
    asm volatile("mbarrier.arrive.expect_tx.shared.b64 _, [%0], %1;" :: "r"((uint32_t)(a)), "r"((uint32_t)(b)) : "memory")
#define MBARRIER_WAIT_PARITY(a, par) do {                                        \
    uint32_t _m = (uint32_t)(a); uint32_t _p = (uint32_t)(par); uint32_t _d;     \
    asm volatile("{\n\t.reg .pred p;\n\t"                                        \
        "mbarrier.try_wait.parity.acquire.cta.shared::cta.b64 p, [%1], %2;\n\t"  \
        "selp.b32 %0, 1, 0, p;\n\t}" : "=r"(_d) : "r"(_m), "r"(_p) : "memory");  \
    if (!_d) {                                                                   \
        asm volatile("{\n\t.reg .pred P1;\n\t"                                   \
        "WL_%=:\n\t"                                                             \
        "mbarrier.try_wait.parity.acquire.cta.shared::cta.b64 P1, [%0], %1, 0x989680;\n\t" \
        "@P1 bra.uni WD_%=;\n\t"                                                 \
        "bra.uni WL_%=;\n\t"                                                     \
        "WD_%=:\n\t}" :: "r"(_m), "r"(_p) : "memory");                           \
    } } while (0)
#define BULK_LD(dst, src, size, mbar) \
    asm volatile("cp.async.bulk.shared::cluster.global.mbarrier::complete_tx::bytes [%0], [%1], %2, [%3];" \
                 :: "r"((uint32_t)(dst)), "l"(src), "r"((uint32_t)(size)), "r"((uint32_t)(mbar)) : "memory")
#define BULK_ST(gd, ss, sz) \
    asm volatile("cp.async.bulk.global.shared::cta.bulk_group [%0], [%1], %2;" \
                 :: "l"(gd), "r"((uint32_t)(ss)), "r"((uint32_t)(sz)) : "memory")
#define BULK_COMMIT() asm volatile("cp.async.bulk.commit_group;" ::: "memory")
#define BULK_WAIT0()  asm volatile("cp.async.bulk.wait_group 0;" ::: "memory")
#define FENCE_ASYNC() asm volatile("fence.proxy.async;" ::: "memory")

__device__ __forceinline__ void ldsm4(uint32_t* r, uint32_t addr) {
    asm volatile("ldmatrix.sync.aligned.m8n8.x4.shared.b16 {%0,%1,%2,%3}, [%4];"
                 : "=r"(r[0]), "=r"(r[1]), "=r"(r[2]), "=r"(r[3]) : "r"(addr));
}
__device__ __forceinline__ void ldsm4t(uint32_t* r, uint32_t addr) {
    asm volatile("ldmatrix.sync.aligned.m8n8.x4.trans.shared.b16 {%0,%1,%2,%3}, [%4];"
                 : "=r"(r[0]), "=r"(r[1]), "=r"(r[2]), "=r"(r[3]) : "r"(addr));
}
__device__ __forceinline__ void mma_f16(float* d, const uint32_t* a,
                                        const uint32_t* b) {
    asm volatile(
        "mma.sync.aligned.m16n8k16.row.col.f32.f16.f16.f32 "
        "{%0,%1,%2,%3},{%4,%5,%6,%7},{%8,%9},{%0,%1,%2,%3};"
        : "+f"(d[0]), "+f"(d[1]), "+f"(d[2]), "+f"(d[3])
        : "r"(a[0]), "r"(a[1]), "r"(a[2]), "r"(a[3]), "r"(b[0]), "r"(b[1]));
}
// FMA-pipe exp2: magic-constant range reduction, no F2I/I2F. x in log2 domain.
__device__ __forceinline__ float fexp2(float x) {
    x = fmaxf(x, -125.0f);
    float y = x + 12582912.0f;
    float fi = y - 12582912.0f;
    float f = x - fi;
    uint32_t iy = __float_as_uint(y);
    float p = 0.0013333558f;
    p = fmaf(p, f, 0.0096181291f);
    p = fmaf(p, f, 0.0555041087f);
    p = fmaf(p, f, 0.2402265070f);
    p = fmaf(p, f, 0.6931471806f);
    p = fmaf(p, f, 1.0f);
    return p * __uint_as_float((iy + 0xB4C0007Fu) << 23);
}

__device__ __forceinline__ void split1h(float x, __half& h, __half& l) {
    h = __float2half_rn(x);
    l = __float2half_rn(x - __half2float(h));
}
__device__ __forceinline__ uint32_t pack_f16(float a, float b) {
    uint32_t w;
    asm("cvt.rn.f16x2.f32 %0, %1, %2;" : "=r"(w) : "f"(b), "f"(a));
    return w;
}

// ===== fp16 HMMA GEMM: 128x128x32, 256 thr, 2-stage, 2 CTA/SM ==============
// A single fp16, B = Wh + Wl split: C = Ah·Bh + Ah·Bl (2 MMAs per fragment).
#define ST_STRIDE 80
#define GOP 10240                     // 128*80 per operand
#define GSTAGE (3 * GOP)              // 30720: A, Bh, Bl
#define GMB (2 * GSTAGE)              // 61440
#define GEMM_SMEM (GMB + 64)

__device__ __forceinline__ void gemm_issue(uint32_t sb, int s,
                                           const char* A,
                                           const char* Bh, const char* Bl,
                                           int row0, int col0, int kb) {
    uint32_t mb = sb + GMB + s * 8;
    uint32_t dst = sb + s * GSTAGE;
    MBARRIER_EXPECT_TX(mb, GSTAGE);
    size_t ao = (size_t)kb * ((size_t)MTOT * 80) + (size_t)row0 * 80;
    size_t bo = (size_t)kb * ((size_t)DM * 80) + (size_t)col0 * 80;
    BULK_LD(dst,           A + ao,  GOP, mb);
    BULK_LD(dst + GOP,     Bh + bo, GOP, mb);
    BULK_LD(dst + 2 * GOP, Bl + bo, GOP, mb);
}

// MODE 0: fp32 out [M,DM].  MODE 2: fp16 out to padded QKV via bulk S2G.
template <int MODE>
__device__ __forceinline__ void gemm_body(const char* __restrict__ A,
                                          const char* __restrict__ Bh,
                                          const char* __restrict__ Bl,
                                          float* __restrict__ Cf,
                                          __half* __restrict__ Chi,
                                          float scale, int row0, int col0) {
    extern __shared__ char sm[];
    const uint32_t sb = smem_u32(sm);
    const int tid = threadIdx.x;
    const int lane = tid & 31;
    const int w = tid >> 5;          // 0..7
    const int wm = w & 1;            // 2 m-warps (64 rows each)
    const int wn = w >> 1;           // 4 n-warps (32 cols each)

    if (tid == 0) {
        MBARRIER_INIT(sb + GMB, 1);
        MBARRIER_INIT(sb + GMB + 8, 1);
    }
    __syncthreads();
    if (tid == 0) {
        gemm_issue(sb, 0, A, Bh, Bl, row0, col0, 0);
        gemm_issue(sb, 1, A, Bh, Bl, row0, col0, 1);
    }

    float acc[4][4][4];
#pragma unroll
    for (int mi = 0; mi < 4; mi++)
#pragma unroll
        for (int ni = 0; ni < 4; ni++)
#pragma unroll
            for (int e = 0; e < 4; e++) acc[mi][ni][e] = 0.f;

    const int a_off = (wm * 64 + (lane & 15)) * ST_STRIDE + (lane >> 4) * 16;
    const int b_off = (wn * 32 + (lane & 7) + ((lane >> 4) << 3)) * ST_STRIDE +
                      ((lane >> 3) & 1) * 16;

    int ph0 = 0, ph1 = 0;
    const int NIT = DM / 32;   // 32
    for (int i = 0; i < NIT; i++) {
        const int s = i & 1;
        if (s == 0) { MBARRIER_WAIT_PARITY(sb + GMB,     ph0); ph0 ^= 1; }
        else        { MBARRIER_WAIT_PARITY(sb + GMB + 8, ph1); ph1 ^= 1; }
        const uint32_t sbase = sb + s * GSTAGE;
#pragma unroll
        for (int ks = 0; ks < 2; ks++) {
            uint32_t ah[4][4], bh[8], bl[8];
            const uint32_t abase = sbase + a_off + ks * 32;
            const uint32_t bbase = sbase + GOP + b_off + ks * 32;
#pragma unroll
            for (int mi = 0; mi < 4; mi++)
                ldsm4(ah[mi], abase + mi * 16 * ST_STRIDE);
#pragma unroll
            for (int p = 0; p < 2; p++) {
                ldsm4(&bh[p * 4], bbase + p * 16 * ST_STRIDE);
                ldsm4(&bl[p * 4], bbase + p * 16 * ST_STRIDE + GOP);
            }
#pragma unroll
            for (int mi = 0; mi < 4; mi++)
#pragma unroll
                for (int ni = 0; ni < 4; ni++) {
                    const uint32_t* fh = &bh[(ni >> 1) * 4 + (ni & 1) * 2];
                    const uint32_t* fl = &bl[(ni >> 1) * 4 + (ni & 1) * 2];
                    mma_f16(acc[mi][ni], ah[mi], fh);
                    mma_f16(acc[mi][ni], ah[mi], fl);
                }
        }
        __syncthreads();
        if (i + 2 < NIT && tid == 0)
            gemm_issue(sb, s, A, Bh, Bl, row0, col0, i + 2);
    }

    const int grp = lane >> 2;
    const int tig = lane & 3;

    if (MODE == 0) {
#pragma unroll
        for (int mi = 0; mi < 4; mi++)
#pragma unroll
            for (int ni = 0; ni < 4; ni++) {
                int col = col0 + wn * 32 + ni * 8 + tig * 2;
                int rlo = row0 + wm * 64 + mi * 16 + grp;
                *reinterpret_cast<float2*>(Cf + (size_t)rlo * DM + col) =
                    make_float2(acc[mi][ni][0], acc[mi][ni][1]);
                *reinterpret_cast<float2*>(Cf + (size_t)(rlo + 8) * DM + col) =
                    make_float2(acc[mi][ni][2], acc[mi][ni][3]);
            }
    } else {
        // smem-stage one head, 18432B blocks, two heads sequentially
        const int b0 = row0 >> 11;
        const int t0 = row0 & (SEQ - 1);
#pragma unroll
        for (int hh = 0; hh < 2; hh++) {
            if ((wn >> 1) == hh) {
                const int lcb = (wn & 1) * 32;
#pragma unroll
                for (int mi = 0; mi < 4; mi++)
#pragma unroll
                    for (int ni = 0; ni < 4; ni++) {
                        int lc2 = (lcb + ni * 8 + tig * 2) * 2;
                        int rr = wm * 64 + mi * 16 + grp;
                        *reinterpret_cast<uint32_t*>(sm + rr * 144 + lc2) =
                            pack_f16(acc[mi][ni][0] * scale, acc[mi][ni][1] * scale);
                        *reinterpret_cast<uint32_t*>(sm + (rr + 8) * 144 + lc2) =
                            pack_f16(acc[mi][ni][2] * scale, acc[mi][ni][3] * scale);
                    }
            }
            __syncthreads();
            if (tid == 0) {
                FENCE_ASYNC();
                int h = (col0 >> 6) + hh;
                size_t off = (((size_t)(b0 * NH + h)) * SEQ + t0) * 144;
                BULK_ST((char*)Chi + off, sb, 18432);
                BULK_COMMIT();
                BULK_WAIT0();
            }
            __syncthreads();
        }
    }
}

__global__ void __launch_bounds__(256, 2)
gemm_qkv_kernel() {
    int z = blockIdx.z;
    const char* A  = g_ah + (size_t)z * ABT;
    const char* Bh = g_wh + (size_t)z * WBT;
    const char* Bl = g_wl + (size_t)z * WBT;
    __half* Chi = (z == 0) ? g_qh : (z == 1) ? g_kh : g_vh;
    float scale = (z == 0) ? 0.125f * 1.4426950408889634f : 1.0f;
    gemm_body<2>(A, Bh, Bl, nullptr, Chi, scale,
                 blockIdx.y * 128, blockIdx.x * 128);
}

__global__ void __launch_bounds__(256, 2)
gemm_o_kernel(float* __restrict__ out) {
    gemm_body<0>(g_aoh, g_wh + 3 * WBT, g_wl + 3 * WBT,
                 out, nullptr, 1.0f,
                 blockIdx.y * 128, blockIdx.x * 128);
}

// ====================== split / transpose kernels ===========================
__global__ void __launch_bounds__(256)
split_act_kernel(const float* __restrict__ q, const float* __restrict__ k,
                 const float* __restrict__ v) {
    int z = blockIdx.z;
    const float* src = (z == 0) ? q : (z == 1) ? k : v;
    size_t i4 = (size_t)blockIdx.x * 256 + threadIdx.x;
    float4 x = reinterpret_cast<const float4*>(src)[i4];
    uint32_t h0 = pack_f16(x.x, x.y);
    uint32_t h1 = pack_f16(x.z, x.w);
    size_t e0 = i4 * 4;
    int m = (int)(e0 >> 10);
    int k0 = (int)(e0 & 1023);
    size_t off = (size_t)z * ABT + (size_t)(k0 >> 5) * ((size_t)MTOT * 80) +
                 (size_t)m * 80 + (size_t)(k0 & 31) * 2;
    *reinterpret_cast<uint2*>(g_ah + off) = make_uint2(h0, h1);
}

__global__ void __launch_bounds__(256)
split_w_kernel(const float* __restrict__ Wq, const float* __restrict__ Wk,
               const float* __restrict__ Wv, const float* __restrict__ Wo) {
    __shared__ float tile[32][33];
    int z = blockIdx.z;
    const float* W = (z == 0) ? Wq : (z == 1) ? Wk : (z == 2) ? Wv : Wo;
    int tx = threadIdx.x & 31, ty = threadIdx.x >> 5;
    int k0 = blockIdx.y * 32, n0 = blockIdx.x * 32;
#pragma unroll
    for (int i = 0; i < 4; i++)
        tile[ty + i * 8][tx] = W[(size_t)(k0 + ty + i * 8) * DM + n0 + tx];
    __syncthreads();
#pragma unroll
    for (int i = 0; i < 4; i++) {
        int n = n0 + ty + i * 8;
        int k = k0 + tx;
        __half h, l;
        split1h(tile[tx][ty + i * 8], h, l);
        size_t off = (size_t)z * WBT + (size_t)(k >> 5) * ((size_t)DM * 80) +
                     (size_t)n * 80 + (size_t)(k & 31) * 2;
        *reinterpret_cast<__half*>(g_wh + off) = h;
        *reinterpret_cast<__half*>(g_wl + off) = l;
    }
}

// ====================== tensorized flash attention ==========================
// Br=128 per CTA (8 warps x 16 rows), 256 threads, 2 CTAs/SM. Bc=64 per iter.
// log2 domain. Q,K,V all single fp16: QK 1 MMA, PV 1 MMA per fragment.
#define FSTR 144
#define FOP  (64 * FSTR)              // 9216
#define FSTAGE (2 * FOP)              // 18432: Kh,Vh
#define QOFF (2 * FSTAGE)             // 36864
#define QOP  (128 * FSTR)             // 18432
#define FBIAS (QOFF + QOP)            // 55296
#define FMB (FBIAS + 512)             // 55808
#define FLASH_SMEM (FMB + 32)

__global__ void __launch_bounds__(256, 2)
flash_kernel(const int* __restrict__ qpm, const int* __restrict__ kpm) {
    extern __shared__ char sm[];
    const uint32_t sb = smem_u32(sm);
    float* biasp = reinterpret_cast<float*>(sm + FBIAS);

    const int tid = threadIdx.x;
    const int lane = tid & 31;
    const int w = tid >> 5;
    const int grp = lane >> 2;
    const int tig = lane & 3;

    const int qt = gridDim.x - 1 - blockIdx.x;
    const int bh = blockIdx.y;
    const int b = bh >> 4;
    const int h = bh & (NH - 1);
    const size_t bbase = (size_t)bh * SEQ * 144;
    const int qrow0 = qt * 128;
    const int nit = 2 * qt + 2;

    if (tid == 0) {
        MBARRIER_INIT(sb + FMB, 1);
        MBARRIER_INIT(sb + FMB + 8, 1);
        MBARRIER_INIT(sb + FMB + 16, 1);
    }
    __syncthreads();
    if (tid == 0) {
        MBARRIER_EXPECT_TX(sb + FMB + 16, QOP);
        BULK_LD(sb + QOFF, (const char*)g_qh + bbase + (size_t)qrow0 * 144, QOP, sb + FMB + 16);
        MBARRIER_EXPECT_TX(sb + FMB, FSTAGE);
        BULK_LD(sb,       (const char*)g_kh + bbase, FOP, sb + FMB);
        BULK_LD(sb + FOP, (const char*)g_vh + bbase, FOP, sb + FMB);
    }

    float o[8][4];
#pragma unroll
    for (int ni = 0; ni < 8; ni++)
#pragma unroll
        for (int e = 0; e < 4; e++) o[ni][e] = 0.f;
    float m0 = -1e30f, m1 = -1e30f, l0 = 0.f, l1 = 0.f;

    const int a_off = (w * 16 + (lane & 15)) * FSTR + (lane >> 4) * 16;
    const int b_off = ((lane & 7) + ((lane >> 4) << 3)) * FSTR +
                      ((lane >> 3) & 1) * 16;
    const int t_off = (lane & 15) * FSTR + ((lane >> 4) << 3) * 2;

    MBARRIER_WAIT_PARITY(sb + FMB + 16, 0);

    int ph0 = 0, ph1 = 0;
    for (int it = 0; it < nit; it++) {
        const int s = it & 1;
        const int krow0 = it * 64;
        const uint32_t stg = sb + s * FSTAGE;

        if (it + 1 < nit && tid == 0) {
            const size_t ko = bbase + (size_t)(it + 1) * 64 * 144;
            const uint32_t mb = sb + FMB + (s ^ 1) * 8;
            const uint32_t d = sb + (s ^ 1) * FSTAGE;
            MBARRIER_EXPECT_TX(mb, FSTAGE);
            BULK_LD(d,       (const char*)g_kh + ko, FOP, mb);
            BULK_LD(d + FOP, (const char*)g_vh + ko, FOP, mb);
        }
        if (tid < 64)
            biasp[s * 64 + tid] =
                (kpm[b * SEQ + krow0 + tid] != 0) ? 0.f : -1e30f;

        if (s == 0) { MBARRIER_WAIT_PARITY(sb + FMB, ph0); ph0 ^= 1; }
        else        { MBARRIER_WAIT_PARITY(sb + FMB + 8, ph1); ph1 ^= 1; }
        __syncthreads();

        // ---- S = Q K^T: 1 MMA per fragment ----
        float sc[8][4];
#pragma unroll
        for (int ni = 0; ni < 8; ni++)
#pragma unroll
            for (int e = 0; e < 4; e++) sc[ni][e] = 0.f;

#pragma unroll
        for (int kd = 0; kd < 4; kd++) {
            uint32_t qfh[4];
            ldsm4(qfh, sb + QOFF + a_off + kd * 32);
            uint32_t kh[4][4];
#pragma unroll
            for (int g = 0; g < 4; g++)
                ldsm4(kh[g], stg + b_off + kd * 32 + g * 16 * FSTR);
#pragma unroll
            for (int ni = 0; ni < 8; ni++) {
                const int g = ni >> 1, sel = (ni & 1) * 2;
                mma_f16(sc[ni], qfh, &kh[g][sel]);
            }
        }

        // ---- bias + causal mask ----
#pragma unroll
        for (int ni = 0; ni < 8; ni++) {
            float2 bb = *reinterpret_cast<float2*>(&biasp[s * 64 + ni * 8 + 2 * tig]);
            sc[ni][0] += bb.x; sc[ni][1] += bb.y;
            sc[ni][2] += bb.x; sc[ni][3] += bb.y;
        }
        if (krow0 + 63 > qrow0) {
            const int r0 = qrow0 + w * 16 + grp;
            const int r1 = r0 + 8;
#pragma unroll
            for (int ni = 0; ni < 8; ni++) {
                int c0 = krow0 + ni * 8 + 2 * tig;
                if (c0 > r0) sc[ni][0] = -1e30f;
                if (c0 + 1 > r0) sc[ni][1] = -1e30f;
                if (c0 > r1) sc[ni][2] = -1e30f;
                if (c0 + 1 > r1) sc[ni][3] = -1e30f;
            }
        }

        // ---- online softmax (log2 domain) ----
        float mx0 = -1e30f, mx1 = -1e30f;
#pragma unroll
        for (int ni = 0; ni < 8; ni++) {
            mx0 = fmaxf(mx0, fmaxf(sc[ni][0], sc[ni][1]));
            mx1 = fmaxf(mx1, fmaxf(sc[ni][2], sc[ni][3]));
        }
        mx0 = fmaxf(mx0, __shfl_xor_sync(0xffffffffu, mx0, 1));
        mx0 = fmaxf(mx0, __shfl_xor_sync(0xffffffffu, mx0, 2));
        mx1 = fmaxf(mx1, __shfl_xor_sync(0xffffffffu, mx1, 1));
        mx1 = fmaxf(mx1, __shfl_xor_sync(0xffffffffu, mx1, 2));
        float mn0 = fmaxf(m0, mx0), mn1 = fmaxf(m1, mx1);
        float cr0 = fexp2(m0 - mn0);
        float cr1 = fexp2(m1 - mn1);
        m0 = mn0; m1 = mn1;
#pragma unroll
        for (int ni = 0; ni < 8; ni++) {
            o[ni][0] *= cr0; o[ni][1] *= cr0;
            o[ni][2] *= cr1; o[ni][3] *= cr1;
        }

        // ---- exp/pack interleaved with PV MMAs ----
        float rs0 = 0.f, rs1 = 0.f;
        uint32_t pa[2][4];
#pragma unroll
        for (int kc = 0; kc < 5; kc++) {
            if (kc < 4) {
                const int par = kc & 1;
#pragma unroll
                for (int j = 0; j < 2; j++) {
                    const int ni = 2 * kc + j;
                    float p0 = fexp2(sc[ni][0] - mn0);
                    float p1 = fexp2(sc[ni][1] - mn0);
                    float p2 = fexp2(sc[ni][2] - mn1);
                    float p3 = fexp2(sc[ni][3] - mn1);
                    rs0 += p0 + p1; rs1 += p2 + p3;
                    pa[par][j * 2]     = pack_f16(p0, p1);
                    pa[par][j * 2 + 1] = pack_f16(p2, p3);
                }
            }
            if (kc > 0) {
                const int kcm = kc - 1;
                const int par = kcm & 1;
                uint32_t vh[4][4];
#pragma unroll
                for (int g = 0; g < 4; g++)
                    ldsm4t(vh[g], stg + FOP + kcm * 16 * FSTR + t_off + g * 32);
#pragma unroll
                for (int ni = 0; ni < 8; ni++) {
                    const int g = ni >> 1, sel = (ni & 1) * 2;
                    mma_f16(o[ni], pa[par], &vh[g][sel]);
                }
            }
        }
        rs0 += __shfl_xor_sync(0xffffffffu, rs0, 1);
        rs0 += __shfl_xor_sync(0xffffffffu, rs0, 2);
        rs1 += __shfl_xor_sync(0xffffffffu, rs1, 1);
        rs1 += __shfl_xor_sync(0xffffffffu, rs1, 2);
        l0 = l0 * cr0 + rs0;
        l1 = l1 * cr1 + rs1;
        __syncthreads();
    }

    // ---- epilogue: /l, query padding, fp16 k-blocked [kb][m][80B] ----
    const int r0 = qrow0 + w * 16 + grp;
    const int r1 = r0 + 8;
    float f0 = (l0 > 0.f ? 1.0f / l0 : 0.f) * (float)qpm[b * SEQ + r0];
    float f1 = (l1 > 0.f ? 1.0f / l1 : 0.f) * (float)qpm[b * SEQ + r1];
    const size_t m0r = (size_t)(b * SEQ + r0);
    const size_t m1r = (size_t)(b * SEQ + r1);
#pragma unroll
    for (int ni = 0; ni < 8; ni++) {
        int col = h * HD + ni * 8 + 2 * tig;
        size_t kslab = (size_t)(col >> 5) * ((size_t)MTOT * 80) +
                       (size_t)(col & 31) * 2;
        *reinterpret_cast<uint32_t*>(g_aoh + kslab + m0r * 80) =
            pack_f16(o[ni][0] * f0, o[ni][1] * f0);
        *reinterpret_cast<uint32_t*>(g_aoh + kslab + m1r * 80) =
            pack_f16(o[ni][2] * f1, o[ni][3] * f1);
    }
}

// ---------------- launch -----------------------------------------------------
extern "C" void kernel_launch(void* const* d_in, const int* in_sizes, int n_in,
                              void* d_out, int out_size) {
    const float* q   = (const float*)d_in[0];
    const float* k   = (const float*)d_in[1];
    const float* v   = (const float*)d_in[2];
    const int*   qpm = (const int*)d_in[3];
    const int*   kpm = (const int*)d_in[4];
    const float* Wq  = (const float*)d_in[5];
    const float* Wk  = (const float*)d_in[6];
    const float* Wv  = (const float*)d_in[7];
    const float* Wo  = (const float*)d_in[8];
    float* out = (float*)d_out;

    dim3 gs((MTOT * DM) / (256 * 4), 1, 3);
    split_act_kernel<<<gs, 256>>>(q, k, v);
    split_w_kernel<<<dim3(32, 32, 4), 256>>>(Wq, Wk, Wv, Wo);

    cudaFuncSetAttribute(gemm_qkv_kernel,
                         cudaFuncAttributeMaxDynamicSharedMemorySize, GEMM_SMEM);
    cudaFuncSetAttribute(gemm_o_kernel,
                         cudaFuncAttributeMaxDynamicSharedMemorySize, GEMM_SMEM);
    gemm_qkv_kernel<<<dim3(DM / 128, MTOT / 128, 3), 256, GEMM_SMEM>>>();

    cudaFuncSetAttribute(flash_kernel,
                         cudaFuncAttributeMaxDynamicSharedMemorySize, FLASH_SMEM);
    flash_kernel<<<dim3(SEQ / 128, NB * NH), 256, FLASH_SMEM>>>(qpm, kpm);

    gemm_o_kernel<<<dim3(DM / 128, MTOT / 128), 256, GEMM_SMEM>>>(out);
}

// round 16
// speedup vs baseline: 1.3222x; 1.3222x over previous
#include <cuda_runtime.h>
#include <cuda_bf16.h>
#include <cuda_fp16.h>
#include <cstdint>
#include <math.h>

#define DM   1024
#define NH   16
#define HD   64
#define SEQ  2048
#define NB   4
#define MTOT (NB * SEQ)   // 8192

// ---------------- global scratch: layouts match smem staging ----------------
#define QKV_ROW 72                         // fp16 elements per padded row (144B)
__device__ __half g_qh[(size_t)NB * NH * SEQ * QKV_ROW];   // Q single fp16
__device__ __half g_kh[(size_t)NB * NH * SEQ * QKV_ROW];   // K single fp16
__device__ __half g_vh[(size_t)NB * NH * SEQ * QKV_ROW];   // V single fp16

#define ABT ((size_t)32 * MTOT * 80)       // one activation tensor, k-blocked
#define WBT ((size_t)32 * DM * 80)         // one weight tensor, k-blocked
__device__ char g_ah[3 * ABT];
__device__ char g_al[3 * ABT];
__device__ char g_wh[4 * WBT];
__device__ char g_wl[4 * WBT];
__device__ char g_aoh[ABT];                // attn-out single fp16, k-blocked

// ============================ helpers =======================================
__device__ __forceinline__ uint32_t smem_u32(const void* p) {
    uint32_t a;
    asm("{ .reg .u64 t; cvta.to.shared.u64 t, %1; cvt.u32.u64 %0, t; }"
        : "=r"(a) : "l"(p));
    return a;
}
#define MBARRIER_INIT(a, c) \
    asm volatile("mbarrier.init.shared.b64 [%0], %1;" :: "r"((uint32_t)(a)), "r"((uint32_t)(c)) : "memory")
#define MBARRIER_EXPECT_TX(a, b) \
    asm volatile("mbarrier.arrive.expect_tx.shared.b64 _, [%0], %1;" :: "r"((uint32_t)(a)), "r"((uint32_t)(b)) : "memory")
#define MBARRIER_WAIT_PARITY(a, par) do {                                        \
    uint32_t _m = (uint32_t)(a); uint32_t _p = (uint32_t)(par); uint32_t _d;     \
    asm volatile("{\n\t.reg .pred p;\n\t"                                        \
        "mbarrier.try_wait.parity.acquire.cta.shared::cta.b64 p, [%1], %2;\n\t"  \
        "selp.b32 %0, 1, 0, p;\n\t}" : "=r"(_d) : "r"(_m), "r"(_p) : "memory");  \
    if (!_d) {                                                                   \
        asm volatile("{\n\t.reg .pred P1;\n\t"                                   \
        "WL_%=:\n\t"                                                             \
        "mbarrier.try_wait.parity.acquire.cta.shared::cta.b64 P1, [%0], %1, 0x989680;\n\t" \
        "@P1 bra.uni WD_%=;\n\t"                                                 \
        "bra.uni WL_%=;\n\t"                                                     \
        "WD_%=:\n\t}" :: "r"(_m), "r"(_p) : "memory");                           \
    } } while (0)
#define BULK_LD(dst, src, size, mbar) \
    asm volatile("cp.async.bulk.shared::cluster.global.mbarrier::complete_tx::bytes [%0], [%1], %2, [%3];" \
                 :: "r"((uint32_t)(dst)), "l"(src), "r"((uint32_t)(size)), "r"((uint32_t)(mbar)) : "memory")
#define BULK_ST(gd, ss, sz) \
    asm volatile("cp.async.bulk.global.shared::cta.bulk_group [%0], [%1], %2;" \
                 :: "l"(gd), "r"((uint32_t)(ss)), "r"((uint32_t)(sz)) : "memory")
#define BULK_COMMIT() asm volatile("cp.async.bulk.commit_group;" ::: "memory")
#define BULK_WAIT0()  asm volatile("cp.async.bulk.wait_group 0;" ::: "memory")
#define FENCE_ASYNC() asm volatile("fence.proxy.async;" ::: "memory")

__device__ __forceinline__ void ldsm4(uint32_t* r, uint32_t addr) {
    asm volatile("ldmatrix.sync.aligned.m8n8.x4.shared.b16 {%0,%1,%2,%3}, [%4];"
                 : "=r"(r[0]), "=r"(r[1]), "=r"(r[2]), "=r"(r[3]) : "r"(addr));
}
__device__ __forceinline__ void ldsm4t(uint32_t* r, uint32_t addr) {
    asm volatile("ldmatrix.sync.aligned.m8n8.x4.trans.shared.b16 {%0,%1,%2,%3}, [%4];"
                 : "=r"(r[0]), "=r"(r[1]), "=r"(r[2]), "=r"(r[3]) : "r"(addr));
}
__device__ __forceinline__ void mma_f16(float* d, const uint32_t* a,
                                        const uint32_t* b) {
    asm volatile(
        "mma.sync.aligned.m16n8k16.row.col.f32.f16.f16.f32 "
        "{%0,%1,%2,%3},{%4,%5,%6,%7},{%8,%9},{%0,%1,%2,%3};"
        : "+f"(d[0]), "+f"(d[1]), "+f"(d[2]), "+f"(d[3])
        : "r"(a[0]), "r"(a[1]), "r"(a[2]), "r"(a[3]), "r"(b[0]), "r"(b[1]));
}
// FMA-pipe exp2: magic-constant range reduction, no F2I/I2F. x in log2 domain.
__device__ __forceinline__ float fexp2(float x) {
    x = fmaxf(x, -125.0f);
    float y = x + 12582912.0f;
    float fi = y - 12582912.0f;
    float f = x - fi;
    uint32_t iy = __float_as_uint(y);
    float p = 0.0013333558f;
    p = fmaf(p, f, 0.0096181291f);
    p = fmaf(p, f, 0.0555041087f);
    p = fmaf(p, f, 0.2402265070f);
    p = fmaf(p, f, 0.6931471806f);
    p = fmaf(p, f, 1.0f);
    return p * __uint_as_float((iy + 0xB4C0007Fu) << 23);
}

__device__ __forceinline__ void split1h(float x, __half& h, __half& l) {
    h = __float2half_rn(x);
    l = __float2half_rn(x - __half2float(h));
}
__device__ __forceinline__ uint32_t pack_f16(float a, float b) {
    uint32_t w;
    asm("cvt.rn.f16x2.f32 %0, %1, %2;" : "=r"(w) : "f"(b), "f"(a));
    return w;
}
__device__ __forceinline__ void split_pack(float a, float b, uint32_t& hw, uint32_t& lw) {
    hw = pack_f16(a, b);
    __half2 h2 = *reinterpret_cast<__half2*>(&hw);
    float la = a - __low2float(h2);
    float lb = b - __high2float(h2);
    lw = pack_f16(la, lb);
}

// ===== fp16 HMMA GEMM: 128x128x32, 256 thr, 2-stage, 2 CTA/SM ==============
// ASPLIT: A hi+lo, B hi+lo -> 3 MMAs (qkv).
// !ASPLIT && BSPLIT: A single, B hi+lo -> 2 MMAs.
// !ASPLIT && !BSPLIT: A single, B single -> 1 MMA (oproj).
#define ST_STRIDE 80
#define GOP 10240                     // 128*80 per operand
#define GSTAGE (4 * GOP)              // 40960 (fixed layout; unused slots skipped)
#define GMB (2 * GSTAGE)              // 81920
#define GEMM_SMEM (GMB + 64)

template <bool ASPLIT, bool BSPLIT>
__device__ __forceinline__ void gemm_issue(uint32_t sb, int s,
                                           const char* Ah, const char* Al,
                                           const char* Bh, const char* Bl,
                                           int row0, int col0, int kb) {
    uint32_t mb = sb + GMB + s * 8;
    uint32_t dst = sb + s * GSTAGE;
    uint32_t bytes = GOP + (ASPLIT ? GOP : 0) + GOP + (BSPLIT ? GOP : 0);
    MBARRIER_EXPECT_TX(mb, bytes);
    size_t ao = (size_t)kb * ((size_t)MTOT * 80) + (size_t)row0 * 80;
    size_t bo = (size_t)kb * ((size_t)DM * 80) + (size_t)col0 * 80;
    BULK_LD(dst,           Ah + ao, GOP, mb);
    if (ASPLIT) BULK_LD(dst + GOP, Al + ao, GOP, mb);
    BULK_LD(dst + 2 * GOP, Bh + bo, GOP, mb);
    if (BSPLIT) BULK_LD(dst + 3 * GOP, Bl + bo, GOP, mb);
}

// MODE 0: fp32 out [M,DM].  MODE 2: fp16 hi out to padded QKV via bulk S2G.
template <int MODE, bool ASPLIT, bool BSPLIT>
__device__ __forceinline__ void gemm_body(const char* __restrict__ Ah,
                                          const char* __restrict__ Al,
                                          const char* __restrict__ Bh,
                                          const char* __restrict__ Bl,
                                          float* __restrict__ Cf,
                                          __half* __restrict__ Chi,
                                          float scale, int row0, int col0) {
    extern __shared__ char sm[];
    const uint32_t sb = smem_u32(sm);
    const int tid = threadIdx.x;
    const int lane = tid & 31;
    const int w = tid >> 5;          // 0..7
    const int wm = w & 1;            // 2 m-warps (64 rows each)
    const int wn = w >> 1;           // 4 n-warps (32 cols each)

    if (tid == 0) {
        MBARRIER_INIT(sb + GMB, 1);
        MBARRIER_INIT(sb + GMB + 8, 1);
    }
    __syncthreads();
    if (tid == 0) {
        gemm_issue<ASPLIT, BSPLIT>(sb, 0, Ah, Al, Bh, Bl, row0, col0, 0);
        gemm_issue<ASPLIT, BSPLIT>(sb, 1, Ah, Al, Bh, Bl, row0, col0, 1);
    }

    float acc[4][4][4];
#pragma unroll
    for (int mi = 0; mi < 4; mi++)
#pragma unroll
        for (int ni = 0; ni < 4; ni++)
#pragma unroll
            for (int e = 0; e < 4; e++) acc[mi][ni][e] = 0.f;

    const int a_off = (wm * 64 + (lane & 15)) * ST_STRIDE + (lane >> 4) * 16;
    const int b_off = (wn * 32 + (lane & 7) + ((lane >> 4) << 3)) * ST_STRIDE +
                      ((lane >> 3) & 1) * 16;

    int ph0 = 0, ph1 = 0;
    const int NIT = DM / 32;   // 32
    for (int i = 0; i < NIT; i++) {
        const int s = i & 1;
        if (s == 0) { MBARRIER_WAIT_PARITY(sb + GMB,     ph0); ph0 ^= 1; }
        else        { MBARRIER_WAIT_PARITY(sb + GMB + 8, ph1); ph1 ^= 1; }
        const uint32_t sbase = sb + s * GSTAGE;
#pragma unroll
        for (int ks = 0; ks < 2; ks++) {
            uint32_t ah[4][4], al[4][4], bh[8], bl[8];
            const uint32_t abase = sbase + a_off + ks * 32;
            const uint32_t bbase = sbase + 2 * GOP + b_off + ks * 32;
#pragma unroll
            for (int mi = 0; mi < 4; mi++) {
                ldsm4(ah[mi], abase + mi * 16 * ST_STRIDE);
                if (ASPLIT) ldsm4(al[mi], abase + mi * 16 * ST_STRIDE + GOP);
            }
#pragma unroll
            for (int p = 0; p < 2; p++) {
                ldsm4(&bh[p * 4], bbase + p * 16 * ST_STRIDE);
                if (BSPLIT) ldsm4(&bl[p * 4], bbase + p * 16 * ST_STRIDE + GOP);
            }
#pragma unroll
            for (int mi = 0; mi < 4; mi++)
#pragma unroll
                for (int ni = 0; ni < 4; ni++) {
                    const uint32_t* fh = &bh[(ni >> 1) * 4 + (ni & 1) * 2];
                    const uint32_t* fl = &bl[(ni >> 1) * 4 + (ni & 1) * 2];
                    mma_f16(acc[mi][ni], ah[mi], fh);
                    if (BSPLIT) mma_f16(acc[mi][ni], ah[mi], fl);
                    if (ASPLIT) mma_f16(acc[mi][ni], al[mi], fh);
                }
        }
        __syncthreads();
        if (i + 2 < NIT && tid == 0)
            gemm_issue<ASPLIT, BSPLIT>(sb, s, Ah, Al, Bh, Bl, row0, col0, i + 2);
    }

    const int grp = lane >> 2;
    const int tig = lane & 3;

    if (MODE == 0) {
#pragma unroll
        for (int mi = 0; mi < 4; mi++)
#pragma unroll
            for (int ni = 0; ni < 4; ni++) {
                int col = col0 + wn * 32 + ni * 8 + tig * 2;
                int rlo = row0 + wm * 64 + mi * 16 + grp;
                *reinterpret_cast<float2*>(Cf + (size_t)rlo * DM + col) =
                    make_float2(acc[mi][ni][0], acc[mi][ni][1]);
                *reinterpret_cast<float2*>(Cf + (size_t)(rlo + 8) * DM + col) =
                    make_float2(acc[mi][ni][2], acc[mi][ni][3]);
            }
    } else {
        // smem-stage one head (hi only), 18432B blocks, two heads sequentially
        const int b0 = row0 >> 11;
        const int t0 = row0 & (SEQ - 1);
#pragma unroll
        for (int hh = 0; hh < 2; hh++) {
            if ((wn >> 1) == hh) {
                const int lcb = (wn & 1) * 32;
#pragma unroll
                for (int mi = 0; mi < 4; mi++)
#pragma unroll
                    for (int ni = 0; ni < 4; ni++) {
                        int lc2 = (lcb + ni * 8 + tig * 2) * 2;
                        int rr = wm * 64 + mi * 16 + grp;
                        *reinterpret_cast<uint32_t*>(sm + rr * 144 + lc2) =
                            pack_f16(acc[mi][ni][0] * scale, acc[mi][ni][1] * scale);
                        *reinterpret_cast<uint32_t*>(sm + (rr + 8) * 144 + lc2) =
                            pack_f16(acc[mi][ni][2] * scale, acc[mi][ni][3] * scale);
                    }
            }
            __syncthreads();
            if (tid == 0) {
                FENCE_ASYNC();
                int h = (col0 >> 6) + hh;
                size_t off = (((size_t)(b0 * NH + h)) * SEQ + t0) * 144;
                BULK_ST((char*)Chi + off, sb, 18432);
                BULK_COMMIT();
                BULK_WAIT0();
            }
            __syncthreads();
        }
    }
}

__global__ void __launch_bounds__(256, 2)
gemm_qkv_kernel() {
    int z = blockIdx.z;
    const char* Ah = g_ah + (size_t)z * ABT;
    const char* Al = g_al + (size_t)z * ABT;
    const char* Bh = g_wh + (size_t)z * WBT;
    const char* Bl = g_wl + (size_t)z * WBT;
    __half* Chi = (z == 0) ? g_qh : (z == 1) ? g_kh : g_vh;
    float scale = (z == 0) ? 0.125f * 1.4426950408889634f : 1.0f;
    gemm_body<2, true, true>(Ah, Al, Bh, Bl, nullptr, Chi, scale,
                             blockIdx.y * 128, blockIdx.x * 128);
}

__global__ void __launch_bounds__(256, 2)
gemm_o_kernel(float* __restrict__ out) {
    gemm_body<0, false, false>(g_aoh, g_aoh, g_wh + 3 * WBT, g_wl + 3 * WBT,
                               out, nullptr, 1.0f,
                               blockIdx.y * 128, blockIdx.x * 128);
}

// ====================== split / transpose kernels ===========================
__global__ void __launch_bounds__(256)
split_act_kernel(const float* __restrict__ q, const float* __restrict__ k,
                 const float* __restrict__ v) {
    int z = blockIdx.z;
    const float* src = (z == 0) ? q : (z == 1) ? k : v;
    size_t i4 = (size_t)blockIdx.x * 256 + threadIdx.x;
    float4 x = reinterpret_cast<const float4*>(src)[i4];
    uint32_t h0, l0, h1, l1;
    split_pack(x.x, x.y, h0, l0);
    split_pack(x.z, x.w, h1, l1);
    size_t e0 = i4 * 4;
    int m = (int)(e0 >> 10);
    int k0 = (int)(e0 & 1023);
    size_t off = (size_t)z * ABT + (size_t)(k0 >> 5) * ((size_t)MTOT * 80) +
                 (size_t)m * 80 + (size_t)(k0 & 31) * 2;
    *reinterpret_cast<uint2*>(g_ah + off) = make_uint2(h0, h1);
    *reinterpret_cast<uint2*>(g_al + off) = make_uint2(l0, l1);
}

__global__ void __launch_bounds__(256)
split_w_kernel(const float* __restrict__ Wq, const float* __restrict__ Wk,
               const float* __restrict__ Wv, const float* __restrict__ Wo) {
    __shared__ float tile[32][33];
    int z = blockIdx.z;
    const float* W = (z == 0) ? Wq : (z == 1) ? Wk : (z == 2) ? Wv : Wo;
    int tx = threadIdx.x & 31, ty = threadIdx.x >> 5;
    int k0 = blockIdx.y * 32, n0 = blockIdx.x * 32;
#pragma unroll
    for (int i = 0; i < 4; i++)
        tile[ty + i * 8][tx] = W[(size_t)(k0 + ty + i * 8) * DM + n0 + tx];
    __syncthreads();
#pragma unroll
    for (int i = 0; i < 4; i++) {
        int n = n0 + ty + i * 8;
        int k = k0 + tx;
        __half h, l;
        split1h(tile[tx][ty + i * 8], h, l);
        size_t off = (size_t)z * WBT + (size_t)(k >> 5) * ((size_t)DM * 80) +
                     (size_t)n * 80 + (size_t)(k & 31) * 2;
        *reinterpret_cast<__half*>(g_wh + off) = h;
        *reinterpret_cast<__half*>(g_wl + off) = l;
    }
}

// ====================== tensorized flash attention ==========================
// Br=128 per CTA (8 warps x 16 rows), 256 threads, 2 CTAs/SM. Bc=64 per iter.
// log2 domain. Q,K,V all single fp16: QK 1 MMA, PV 1 MMA per fragment.
#define FSTR 144
#define FOP  (64 * FSTR)              // 9216
#define FSTAGE (2 * FOP)              // 18432: Kh,Vh
#define QOFF (2 * FSTAGE)             // 36864
#define QOP  (128 * FSTR)             // 18432
#define FBIAS (QOFF + QOP)            // 55296
#define FMB (FBIAS + 512)             // 55808
#define FLASH_SMEM (FMB + 32)

__global__ void __launch_bounds__(256, 2)
flash_kernel(const int* __restrict__ qpm, const int* __restrict__ kpm) {
    extern __shared__ char sm[];
    const uint32_t sb = smem_u32(sm);
    float* biasp = reinterpret_cast<float*>(sm + FBIAS);

    const int tid = threadIdx.x;
    const int lane = tid & 31;
    const int w = tid >> 5;
    const int grp = lane >> 2;
    const int tig = lane & 3;

    const int qt = gridDim.x - 1 - blockIdx.x;
    const int bh = blockIdx.y;
    const int b = bh >> 4;
    const int h = bh & (NH - 1);
    const size_t bbase = (size_t)bh * SEQ * 144;
    const int qrow0 = qt * 128;
    const int nit = 2 * qt + 2;

    if (tid == 0) {
        MBARRIER_INIT(sb + FMB, 1);
        MBARRIER_INIT(sb + FMB + 8, 1);
        MBARRIER_INIT(sb + FMB + 16, 1);
    }
    __syncthreads();
    if (tid == 0) {
        MBARRIER_EXPECT_TX(sb + FMB + 16, QOP);
        BULK_LD(sb + QOFF, (const char*)g_qh + bbase + (size_t)qrow0 * 144, QOP, sb + FMB + 16);
        MBARRIER_EXPECT_TX(sb + FMB, FSTAGE);
        BULK_LD(sb,       (const char*)g_kh + bbase, FOP, sb + FMB);
        BULK_LD(sb + FOP, (const char*)g_vh + bbase, FOP, sb + FMB);
    }

    float o[8][4];
#pragma unroll
    for (int ni = 0; ni < 8; ni++)
#pragma unroll
        for (int e = 0; e < 4; e++) o[ni][e] = 0.f;
    float m0 = -1e30f, m1 = -1e30f, l0 = 0.f, l1 = 0.f;

    const int a_off = (w * 16 + (lane & 15)) * FSTR + (lane >> 4) * 16;
    const int b_off = ((lane & 7) + ((lane >> 4) << 3)) * FSTR +
                      ((lane >> 3) & 1) * 16;
    const int t_off = (lane & 15) * FSTR + ((lane >> 4) << 3) * 2;

    MBARRIER_WAIT_PARITY(sb + FMB + 16, 0);

    int ph0 = 0, ph1 = 0;
    for (int it = 0; it < nit; it++) {
        const int s = it & 1;
        const int krow0 = it * 64;
        const uint32_t stg = sb + s * FSTAGE;

        if (it + 1 < nit && tid == 0) {
            const size_t ko = bbase + (size_t)(it + 1) * 64 * 144;
            const uint32_t mb = sb + FMB + (s ^ 1) * 8;
            const uint32_t d = sb + (s ^ 1) * FSTAGE;
            MBARRIER_EXPECT_TX(mb, FSTAGE);
            BULK_LD(d,       (const char*)g_kh + ko, FOP, mb);
            BULK_LD(d + FOP, (const char*)g_vh + ko, FOP, mb);
        }
        if (tid < 64)
            biasp[s * 64 + tid] =
                (kpm[b * SEQ + krow0 + tid] != 0) ? 0.f : -1e30f;

        if (s == 0) { MBARRIER_WAIT_PARITY(sb + FMB, ph0); ph0 ^= 1; }
        else        { MBARRIER_WAIT_PARITY(sb + FMB + 8, ph1); ph1 ^= 1; }
        __syncthreads();

        // ---- S = Q K^T: 1 MMA per fragment ----
        float sc[8][4];
#pragma unroll
        for (int ni = 0; ni < 8; ni++)
#pragma unroll
            for (int e = 0; e < 4; e++) sc[ni][e] = 0.f;

#pragma unroll
        for (int kd = 0; kd < 4; kd++) {
            uint32_t qfh[4];
            ldsm4(qfh, sb + QOFF + a_off + kd * 32);
            uint32_t kh[4][4];
#pragma unroll
            for (int g = 0; g < 4; g++)
                ldsm4(kh[g], stg + b_off + kd * 32 + g * 16 * FSTR);
#pragma unroll
            for (int ni = 0; ni < 8; ni++) {
                const int g = ni >> 1, sel = (ni & 1) * 2;
                mma_f16(sc[ni], qfh, &kh[g][sel]);
            }
        }

        // ---- bias + causal mask ----
#pragma unroll
        for (int ni = 0; ni < 8; ni++) {
            float2 bb = *reinterpret_cast<float2*>(&biasp[s * 64 + ni * 8 + 2 * tig]);
            sc[ni][0] += bb.x; sc[ni][1] += bb.y;
            sc[ni][2] += bb.x; sc[ni][3] += bb.y;
        }
        if (krow0 + 63 > qrow0) {
            const int r0 = qrow0 + w * 16 + grp;
            const int r1 = r0 + 8;
#pragma unroll
            for (int ni = 0; ni < 8; ni++) {
                int c0 = krow0 + ni * 8 + 2 * tig;
                if (c0 > r0) sc[ni][0] = -1e30f;
                if (c0 + 1 > r0) sc[ni][1] = -1e30f;
                if (c0 > r1) sc[ni][2] = -1e30f;
                if (c0 + 1 > r1) sc[ni][3] = -1e30f;
            }
        }

        // ---- online softmax (log2 domain) ----
        float mx0 = -1e30f, mx1 = -1e30f;
#pragma unroll
        for (int ni = 0; ni < 8; ni++) {
            mx0 = fmaxf(mx0, fmaxf(sc[ni][0], sc[ni][1]));
            mx1 = fmaxf(mx1, fmaxf(sc[ni][2], sc[ni][3]));
        }
        mx0 = fmaxf(mx0, __shfl_xor_sync(0xffffffffu, mx0, 1));
        mx0 = fmaxf(mx0, __shfl_xor_sync(0xffffffffu, mx0, 2));
        mx1 = fmaxf(mx1, __shfl_xor_sync(0xffffffffu, mx1, 1));
        mx1 = fmaxf(mx1, __shfl_xor_sync(0xffffffffu, mx1, 2));
        float mn0 = fmaxf(m0, mx0), mn1 = fmaxf(m1, mx1);
        float cr0 = fexp2(m0 - mn0);
        float cr1 = fexp2(m1 - mn1);
        m0 = mn0; m1 = mn1;
#pragma unroll
        for (int ni = 0; ni < 8; ni++) {
            o[ni][0] *= cr0; o[ni][1] *= cr0;
            o[ni][2] *= cr1; o[ni][3] *= cr1;
        }

        // ---- exp/pack interleaved with PV MMAs ----
        float rs0 = 0.f, rs1 = 0.f;
        uint32_t pa[2][4];
#pragma unroll
        for (int kc = 0; kc < 5; kc++) {
            if (kc < 4) {
                const int par = kc & 1;
#pragma unroll
                for (int j = 0; j < 2; j++) {
                    const int ni = 2 * kc + j;
                    float p0 = fexp2(sc[ni][0] - mn0);
                    float p1 = fexp2(sc[ni][1] - mn0);
                    float p2 = fexp2(sc[ni][2] - mn1);
                    float p3 = fexp2(sc[ni][3] - mn1);
                    rs0 += p0 + p1; rs1 += p2 + p3;
                    pa[par][j * 2]     = pack_f16(p0, p1);
                    pa[par][j * 2 + 1] = pack_f16(p2, p3);
                }
            }
            if (kc > 0) {
                const int kcm = kc - 1;
                const int par = kcm & 1;
                uint32_t vh[4][4];
#pragma unroll
                for (int g = 0; g < 4; g++)
                    ldsm4t(vh[g], stg + FOP + kcm * 16 * FSTR + t_off + g * 32);
#pragma unroll
                for (int ni = 0; ni < 8; ni++) {
                    const int g = ni >> 1, sel = (ni & 1) * 2;
                    mma_f16(o[ni], pa[par], &vh[g][sel]);
                }
            }
        }
        rs0 += __shfl_xor_sync(0xffffffffu, rs0, 1);
        rs0 += __shfl_xor_sync(0xffffffffu, rs0, 2);
        rs1 += __shfl_xor_sync(0xffffffffu, rs1, 1);
        rs1 += __shfl_xor_sync(0xffffffffu, rs1, 2);
        l0 = l0 * cr0 + rs0;
        l1 = l1 * cr1 + rs1;
        __syncthreads();
    }

    // ---- epilogue: /l, query padding, fp16 k-blocked [kb][m][80B] ----
    const int r0 = qrow0 + w * 16 + grp;
    const int r1 = r0 + 8;
    float f0 = (l0 > 0.f ? 1.0f / l0 : 0.f) * (float)qpm[b * SEQ + r0];
    float f1 = (l1 > 0.f ? 1.0f / l1 : 0.f) * (float)qpm[b * SEQ + r1];
    const size_t m0r = (size_t)(b * SEQ + r0);
    const size_t m1r = (size_t)(b * SEQ + r1);
#pragma unroll
    for (int ni = 0; ni < 8; ni++) {
        int col = h * HD + ni * 8 + 2 * tig;
        size_t kslab = (size_t)(col >> 5) * ((size_t)MTOT * 80) +
                       (size_t)(col & 31) * 2;
        *reinterpret_cast<uint32_t*>(g_aoh + kslab + m0r * 80) =
            pack_f16(o[ni][0] * f0, o[ni][1] * f0);
        *reinterpret_cast<uint32_t*>(g_aoh + kslab + m1r * 80) =
            pack_f16(o[ni][2] * f1, o[ni][3] * f1);
    }
}

// ---------------- launch -----------------------------------------------------
extern "C" void kernel_launch(void* const* d_in, const int* in_sizes, int n_in,
                              void* d_out, int out_size) {
    const float* q   = (const float*)d_in[0];
    const float* k   = (const float*)d_in[1];
    const float* v   = (const float*)d_in[2];
    const int*   qpm = (const int*)d_in[3];
    const int*   kpm = (const int*)d_in[4];
    const float* Wq  = (const float*)d_in[5];
    const float* Wk  = (const float*)d_in[6];
    const float* Wv  = (const float*)d_in[7];
    const float* Wo  = (const float*)d_in[8];
    float* out = (float*)d_out;

    dim3 gs((MTOT * DM) / (256 * 4), 1, 3);
    split_act_kernel<<<gs, 256>>>(q, k, v);
    split_w_kernel<<<dim3(32, 32, 4), 256>>>(Wq, Wk, Wv, Wo);

    cudaFuncSetAttribute(gemm_qkv_kernel,
                         cudaFuncAttributeMaxDynamicSharedMemorySize, GEMM_SMEM);
    cudaFuncSetAttribute(gemm_o_kernel,
                         cudaFuncAttributeMaxDynamicSharedMemorySize, GEMM_SMEM);
    gemm_qkv_kernel<<<dim3(DM / 128, MTOT / 128, 3), 256, GEMM_SMEM>>>();

    cudaFuncSetAttribute(flash_kernel,
                         cudaFuncAttributeMaxDynamicSharedMemorySize, FLASH_SMEM);
    flash_kernel<<<dim3(SEQ / 128, NB * NH), 256, FLASH_SMEM>>>(qpm, kpm);

    gemm_o_kernel<<<dim3(DM / 128, MTOT / 128), 256, GEMM_SMEM>>>(out);
}

// round 17
// speedup vs baseline: 1.6298x; 1.2326x over previous
#include <cuda_runtime.h>
#include <cuda_bf16.h>
#include <cuda_fp16.h>
#include <cstdint>
#include <math.h>

#define DM   1024
#define NH   16
#define HD   64
#define SEQ  2048
#define NB   4
#define MTOT (NB * SEQ)   // 8192

// ---------------- global scratch: layouts match smem staging ----------------
#define QKV_ROW 72                         // fp16 elements per padded row (144B)
__device__ __half g_qh[(size_t)NB * NH * SEQ * QKV_ROW];   // Q single fp16
__device__ __half g_kh[(size_t)NB * NH * SEQ * QKV_ROW];   // K single fp16
__device__ __half g_vh[(size_t)NB * NH * SEQ * QKV_ROW];   // V single fp16 (+ones col at dh=64)

#define ABT ((size_t)32 * MTOT * 80)       // one activation tensor, k-blocked
#define WBT ((size_t)32 * DM * 80)         // one weight tensor, k-blocked
__device__ char g_ah[3 * ABT];             // activations single fp16
__device__ char g_wh[4 * WBT];
__device__ char g_wl[4 * WBT];
__device__ char g_aoh[ABT];                // attn-out single fp16, k-blocked

// ============================ helpers =======================================
__device__ __forceinline__ uint32_t smem_u32(const void* p) {
    uint32_t a;
    asm("{ .reg .u64 t; cvta.to.shared.u64 t, %1; cvt.u32.u64 %0, t; }"
        : "=r"(a) : "l"(p));
    return a;
}
#define MBARRIER_INIT(a, c) \
    asm volatile("mbarrier.init.shared.b64 [%0], %1;" :: "r"((uint32_t)(a)), "r"((uint32_t)(c)) : "memory")
#define MBARRIER_EXPECT_TX(a, b) \
    asm volatile("mbarrier.arrive.expect_tx.shared.b64 _, [%0], %1;" :: "r"((uint32_t)(a)), "r"((uint32_t)(b)) : "memory")
#define MBARRIER_WAIT_PARITY(a, par) do {                                        \
    uint32_t _m = (uint32_t)(a); uint32_t _p = (uint32_t)(par); uint32_t _d;     \
    asm volatile("{\n\t.reg .pred p;\n\t"                                        \
        "mbarrier.try_wait.parity.acquire.cta.shared::cta.b64 p, [%1], %2;\n\t"  \
        "selp.b32 %0, 1, 0, p;\n\t}" : "=r"(_d) : "r"(_m), "r"(_p) : "memory");  \
    if (!_d) {                                                                   \
        asm volatile("{\n\t.reg .pred P1;\n\t"                                   \
        "WL_%=:\n\t"                                                             \
        "mbarrier.try_wait.parity.acquire.cta.shared::cta.b64 P1, [%0], %1, 0x989680;\n\t" \
        "@P1 bra.uni WD_%=;\n\t"                                                 \
        "bra.uni WL_%=;\n\t"                                                     \
        "WD_%=:\n\t}" :: "r"(_m), "r"(_p) : "memory");                           \
    } } while (0)
#define BULK_LD(dst, src, size, mbar) \
    asm volatile("cp.async.bulk.shared::cluster.global.mbarrier::complete_tx::bytes [%0], [%1], %2, [%3];" \
                 :: "r"((uint32_t)(dst)), "l"(src), "r"((uint32_t)(size)), "r"((uint32_t)(mbar)) : "memory")
#define BULK_ST(gd, ss, sz) \
    asm volatile("cp.async.bulk.global.shared::cta.bulk_group [%0], [%1], %2;" \
                 :: "l"(gd), "r"((uint32_t)(ss)), "r"((uint32_t)(sz)) : "memory")
#define BULK_COMMIT() asm volatile("cp.async.bulk.commit_group;" ::: "memory")
#define BULK_WAIT0()  asm volatile("cp.async.bulk.wait_group 0;" ::: "memory")
#define FENCE_ASYNC() asm volatile("fence.proxy.async;" ::: "memory")

__device__ __forceinline__ void ldsm4(uint32_t* r, uint32_t addr) {
    asm volatile("ldmatrix.sync.aligned.m8n8.x4.shared.b16 {%0,%1,%2,%3}, [%4];"
                 : "=r"(r[0]), "=r"(r[1]), "=r"(r[2]), "=r"(r[3]) : "r"(addr));
}
__device__ __forceinline__ void ldsm4t(uint32_t* r, uint32_t addr) {
    asm volatile("ldmatrix.sync.aligned.m8n8.x4.trans.shared.b16 {%0,%1,%2,%3}, [%4];"
                 : "=r"(r[0]), "=r"(r[1]), "=r"(r[2]), "=r"(r[3]) : "r"(addr));
}
__device__ __forceinline__ void mma_f16(float* d, const uint32_t* a,
                                        const uint32_t* b) {
    asm volatile(
        "mma.sync.aligned.m16n8k16.row.col.f32.f16.f16.f32 "
        "{%0,%1,%2,%3},{%4,%5,%6,%7},{%8,%9},{%0,%1,%2,%3};"
        : "+f"(d[0]), "+f"(d[1]), "+f"(d[2]), "+f"(d[3])
        : "r"(a[0]), "r"(a[1]), "r"(a[2]), "r"(a[3]), "r"(b[0]), "r"(b[1]));
}
// FMA-pipe exp2: magic-constant range reduction, no F2I/I2F. x in log2 domain.
__device__ __forceinline__ float fexp2(float x) {
    x = fmaxf(x, -125.0f);
    float y = x + 12582912.0f;
    float fi = y - 12582912.0f;
    float f = x - fi;
    uint32_t iy = __float_as_uint(y);
    float p = 0.0013333558f;
    p = fmaf(p, f, 0.0096181291f);
    p = fmaf(p, f, 0.0555041087f);
    p = fmaf(p, f, 0.2402265070f);
    p = fmaf(p, f, 0.6931471806f);
    p = fmaf(p, f, 1.0f);
    return p * __uint_as_float((iy + 0xB4C0007Fu) << 23);
}

__device__ __forceinline__ void split1h(float x, __half& h, __half& l) {
    h = __float2half_rn(x);
    l = __float2half_rn(x - __half2float(h));
}
__device__ __forceinline__ uint32_t pack_f16(float a, float b) {
    uint32_t w;
    asm("cvt.rn.f16x2.f32 %0, %1, %2;" : "=r"(w) : "f"(b), "f"(a));
    return w;
}

// ===== fp16 HMMA GEMM: 128x128x32, 256 thr, 2-stage, 2 CTA/SM ==============
// BSPLIT: B = Wh + Wl (2 MMAs). !BSPLIT: 1 MMA. A always single fp16.
#define ST_STRIDE 80
#define GOP 10240                     // 128*80 per operand
#define GSTAGE (3 * GOP)              // 30720: A, Bh, Bl
#define GMB (2 * GSTAGE)              // 61440
#define GEMM_SMEM (GMB + 64)

template <bool BSPLIT>
__device__ __forceinline__ void gemm_issue(uint32_t sb, int s,
                                           const char* A,
                                           const char* Bh, const char* Bl,
                                           int row0, int col0, int kb) {
    uint32_t mb = sb + GMB + s * 8;
    uint32_t dst = sb + s * GSTAGE;
    MBARRIER_EXPECT_TX(mb, BSPLIT ? GSTAGE : 2 * GOP);
    size_t ao = (size_t)kb * ((size_t)MTOT * 80) + (size_t)row0 * 80;
    size_t bo = (size_t)kb * ((size_t)DM * 80) + (size_t)col0 * 80;
    BULK_LD(dst,           A + ao,  GOP, mb);
    BULK_LD(dst + GOP,     Bh + bo, GOP, mb);
    if (BSPLIT) BULK_LD(dst + 2 * GOP, Bl + bo, GOP, mb);
}

// MODE 0: fp32 out [M,DM].  MODE 2: fp16 out to padded QKV (pad gets pad_w).
template <int MODE, bool BSPLIT>
__device__ __forceinline__ void gemm_body(const char* __restrict__ A,
                                          const char* __restrict__ Bh,
                                          const char* __restrict__ Bl,
                                          float* __restrict__ Cf,
                                          __half* __restrict__ Chi,
                                          float scale, uint32_t pad_w,
                                          int row0, int col0) {
    extern __shared__ char sm[];
    const uint32_t sb = smem_u32(sm);
    const int tid = threadIdx.x;
    const int lane = tid & 31;
    const int w = tid >> 5;          // 0..7
    const int wm = w & 1;            // 2 m-warps (64 rows each)
    const int wn = w >> 1;           // 4 n-warps (32 cols each)

    if (tid == 0) {
        MBARRIER_INIT(sb + GMB, 1);
        MBARRIER_INIT(sb + GMB + 8, 1);
    }
    __syncthreads();
    if (tid == 0) {
        gemm_issue<BSPLIT>(sb, 0, A, Bh, Bl, row0, col0, 0);
        gemm_issue<BSPLIT>(sb, 1, A, Bh, Bl, row0, col0, 1);
    }

    float acc[4][4][4];
#pragma unroll
    for (int mi = 0; mi < 4; mi++)
#pragma unroll
        for (int ni = 0; ni < 4; ni++)
#pragma unroll
            for (int e = 0; e < 4; e++) acc[mi][ni][e] = 0.f;

    const int a_off = (wm * 64 + (lane & 15)) * ST_STRIDE + (lane >> 4) * 16;
    const int b_off = (wn * 32 + (lane & 7) + ((lane >> 4) << 3)) * ST_STRIDE +
                      ((lane >> 3) & 1) * 16;

    int ph0 = 0, ph1 = 0;
    const int NIT = DM / 32;   // 32
    for (int i = 0; i < NIT; i++) {
        const int s = i & 1;
        if (s == 0) { MBARRIER_WAIT_PARITY(sb + GMB,     ph0); ph0 ^= 1; }
        else        { MBARRIER_WAIT_PARITY(sb + GMB + 8, ph1); ph1 ^= 1; }
        const uint32_t sbase = sb + s * GSTAGE;
#pragma unroll
        for (int ks = 0; ks < 2; ks++) {
            uint32_t ah[4][4], bh[8], bl[8];
            const uint32_t abase = sbase + a_off + ks * 32;
            const uint32_t bbase = sbase + GOP + b_off + ks * 32;
#pragma unroll
            for (int mi = 0; mi < 4; mi++)
                ldsm4(ah[mi], abase + mi * 16 * ST_STRIDE);
#pragma unroll
            for (int p = 0; p < 2; p++) {
                ldsm4(&bh[p * 4], bbase + p * 16 * ST_STRIDE);
                if (BSPLIT) ldsm4(&bl[p * 4], bbase + p * 16 * ST_STRIDE + GOP);
            }
#pragma unroll
            for (int mi = 0; mi < 4; mi++)
#pragma unroll
                for (int ni = 0; ni < 4; ni++) {
                    const uint32_t* fh = &bh[(ni >> 1) * 4 + (ni & 1) * 2];
                    const uint32_t* fl = &bl[(ni >> 1) * 4 + (ni & 1) * 2];
                    mma_f16(acc[mi][ni], ah[mi], fh);
                    if (BSPLIT) mma_f16(acc[mi][ni], ah[mi], fl);
                }
        }
        __syncthreads();
        if (i + 2 < NIT && tid == 0)
            gemm_issue<BSPLIT>(sb, s, A, Bh, Bl, row0, col0, i + 2);
    }

    const int grp = lane >> 2;
    const int tig = lane & 3;

    if (MODE == 0) {
#pragma unroll
        for (int mi = 0; mi < 4; mi++)
#pragma unroll
            for (int ni = 0; ni < 4; ni++) {
                int col = col0 + wn * 32 + ni * 8 + tig * 2;
                int rlo = row0 + wm * 64 + mi * 16 + grp;
                *reinterpret_cast<float2*>(Cf + (size_t)rlo * DM + col) =
                    make_float2(acc[mi][ni][0], acc[mi][ni][1]);
                *reinterpret_cast<float2*>(Cf + (size_t)(rlo + 8) * DM + col) =
                    make_float2(acc[mi][ni][2], acc[mi][ni][3]);
            }
    } else {
        // smem-stage one head, 18432B blocks, two heads sequentially
        const int b0 = row0 >> 11;
        const int t0 = row0 & (SEQ - 1);
#pragma unroll
        for (int hh = 0; hh < 2; hh++) {
            if ((wn >> 1) == hh) {
                const int lcb = (wn & 1) * 32;
#pragma unroll
                for (int mi = 0; mi < 4; mi++) {
#pragma unroll
                    for (int ni = 0; ni < 4; ni++) {
                        int lc2 = (lcb + ni * 8 + tig * 2) * 2;
                        int rr = wm * 64 + mi * 16 + grp;
                        *reinterpret_cast<uint32_t*>(sm + rr * 144 + lc2) =
                            pack_f16(acc[mi][ni][0] * scale, acc[mi][ni][1] * scale);
                        *reinterpret_cast<uint32_t*>(sm + (rr + 8) * 144 + lc2) =
                            pack_f16(acc[mi][ni][2] * scale, acc[mi][ni][3] * scale);
                    }
                    // pad bytes 128..143: ones column (V) or zeros (Q,K)
                    if (tig == 0 && (wn & 1) == 0) {
                        int rr = wm * 64 + mi * 16 + grp;
                        *reinterpret_cast<uint4*>(sm + rr * 144 + 128) =
                            make_uint4(pad_w, 0, 0, 0);
                        *reinterpret_cast<uint4*>(sm + (rr + 8) * 144 + 128) =
                            make_uint4(pad_w, 0, 0, 0);
                    }
                }
            }
            __syncthreads();
            if (tid == 0) {
                FENCE_ASYNC();
                int h = (col0 >> 6) + hh;
                size_t off = (((size_t)(b0 * NH + h)) * SEQ + t0) * 144;
                BULK_ST((char*)Chi + off, sb, 18432);
                BULK_COMMIT();
                BULK_WAIT0();
            }
            __syncthreads();
        }
    }
}

__global__ void __launch_bounds__(256, 2)
gemm_qkv_kernel() {
    int z = blockIdx.z;
    const char* A  = g_ah + (size_t)z * ABT;
    const char* Bh = g_wh + (size_t)z * WBT;
    const char* Bl = g_wl + (size_t)z * WBT;
    __half* Chi = (z == 0) ? g_qh : (z == 1) ? g_kh : g_vh;
    float scale = (z == 0) ? 0.125f * 1.4426950408889634f : 1.0f;
    uint32_t pad_w = (z == 2) ? 0x00003C00u : 0u;   // V: 1.0h at dh=64
    gemm_body<2, true>(A, Bh, Bl, nullptr, Chi, scale, pad_w,
                       blockIdx.y * 128, blockIdx.x * 128);
}

__global__ void __launch_bounds__(256, 2)
gemm_o_kernel(float* __restrict__ out) {
    gemm_body<0, false>(g_aoh, g_wh + 3 * WBT, g_wl + 3 * WBT,
                        out, nullptr, 1.0f, 0u,
                        blockIdx.y * 128, blockIdx.x * 128);
}

// ====================== split / transpose kernels ===========================
__global__ void __launch_bounds__(256)
split_act_kernel(const float* __restrict__ q, const float* __restrict__ k,
                 const float* __restrict__ v) {
    int z = blockIdx.z;
    const float* src = (z == 0) ? q : (z == 1) ? k : v;
    size_t i4 = (size_t)blockIdx.x * 256 + threadIdx.x;
    float4 x = reinterpret_cast<const float4*>(src)[i4];
    uint32_t h0 = pack_f16(x.x, x.y);
    uint32_t h1 = pack_f16(x.z, x.w);
    size_t e0 = i4 * 4;
    int m = (int)(e0 >> 10);
    int k0 = (int)(e0 & 1023);
    size_t off = (size_t)z * ABT + (size_t)(k0 >> 5) * ((size_t)MTOT * 80) +
                 (size_t)m * 80 + (size_t)(k0 & 31) * 2;
    *reinterpret_cast<uint2*>(g_ah + off) = make_uint2(h0, h1);
}

__global__ void __launch_bounds__(256)
split_w_kernel(const float* __restrict__ Wq, const float* __restrict__ Wk,
               const float* __restrict__ Wv, const float* __restrict__ Wo) {
    __shared__ float tile[32][33];
    int z = blockIdx.z;
    const float* W = (z == 0) ? Wq : (z == 1) ? Wk : (z == 2) ? Wv : Wo;
    int tx = threadIdx.x & 31, ty = threadIdx.x >> 5;
    int k0 = blockIdx.y * 32, n0 = blockIdx.x * 32;
#pragma unroll
    for (int i = 0; i < 4; i++)
        tile[ty + i * 8][tx] = W[(size_t)(k0 + ty + i * 8) * DM + n0 + tx];
    __syncthreads();
#pragma unroll
    for (int i = 0; i < 4; i++) {
        int n = n0 + ty + i * 8;
        int k = k0 + tx;
        __half h, l;
        split1h(tile[tx][ty + i * 8], h, l);
        size_t off = (size_t)z * WBT + (size_t)(k >> 5) * ((size_t)DM * 80) +
                     (size_t)n * 80 + (size_t)(k & 31) * 2;
        *reinterpret_cast<__half*>(g_wh + off) = h;
        *reinterpret_cast<__half*>(g_wl + off) = l;
    }
}

// ====================== tensorized flash attention ==========================
// Br=128 per CTA (8 warps x 16 rows), 256 threads, 2 CTAs/SM. Bc=64 per iter.
// log2 domain. Q,K,V single fp16. Row-sum via ones-column in V pad (dh=64).
#define FSTR 144
#define FOP  (64 * FSTR)              // 9216
#define FSTAGE (2 * FOP)              // 18432: Kh,Vh
#define QOFF (2 * FSTAGE)             // 36864
#define QOP  (128 * FSTR)             // 18432
#define FBIAS (QOFF + QOP)            // 55296
#define FMB (FBIAS + 512)             // 55808
#define FLASH_SMEM (FMB + 32)

__global__ void __launch_bounds__(256, 2)
flash_kernel(const int* __restrict__ qpm, const int* __restrict__ kpm) {
    extern __shared__ char sm[];
    const uint32_t sb = smem_u32(sm);
    float* biasp = reinterpret_cast<float*>(sm + FBIAS);

    const int tid = threadIdx.x;
    const int lane = tid & 31;
    const int w = tid >> 5;
    const int grp = lane >> 2;
    const int tig = lane & 3;

    const int qt = gridDim.x - 1 - blockIdx.x;
    const int bh = blockIdx.y;
    const int b = bh >> 4;
    const int h = bh & (NH - 1);
    const size_t bbase = (size_t)bh * SEQ * 144;
    const int qrow0 = qt * 128;
    const int nit = 2 * qt + 2;

    if (tid == 0) {
        MBARRIER_INIT(sb + FMB, 1);
        MBARRIER_INIT(sb + FMB + 8, 1);
        MBARRIER_INIT(sb + FMB + 16, 1);
    }
    __syncthreads();
    if (tid == 0) {
        MBARRIER_EXPECT_TX(sb + FMB + 16, QOP);
        BULK_LD(sb + QOFF, (const char*)g_qh + bbase + (size_t)qrow0 * 144, QOP, sb + FMB + 16);
        MBARRIER_EXPECT_TX(sb + FMB, FSTAGE);
        BULK_LD(sb,       (const char*)g_kh + bbase, FOP, sb + FMB);
        BULK_LD(sb + FOP, (const char*)g_vh + bbase, FOP, sb + FMB);
    }

    float o[8][4];
#pragma unroll
    for (int ni = 0; ni < 8; ni++)
#pragma unroll
        for (int e = 0; e < 4; e++) o[ni][e] = 0.f;
    float o9[4] = {0.f, 0.f, 0.f, 0.f};     // ones-column accumulator (row sums)
    float m0 = -1e30f, m1 = -1e30f;

    const int a_off = (w * 16 + (lane & 15)) * FSTR + (lane >> 4) * 16;
    const int b_off = ((lane & 7) + ((lane >> 4) << 3)) * FSTR +
                      ((lane >> 3) & 1) * 16;
    const int t_off = (lane & 15) * FSTR + ((lane >> 4) << 3) * 2;

    MBARRIER_WAIT_PARITY(sb + FMB + 16, 0);

    int ph0 = 0, ph1 = 0;
    for (int it = 0; it < nit; it++) {
        const int s = it & 1;
        const int krow0 = it * 64;
        const uint32_t stg = sb + s * FSTAGE;

        if (it + 1 < nit && tid == 0) {
            const size_t ko = bbase + (size_t)(it + 1) * 64 * 144;
            const uint32_t mb = sb + FMB + (s ^ 1) * 8;
            const uint32_t d = sb + (s ^ 1) * FSTAGE;
            MBARRIER_EXPECT_TX(mb, FSTAGE);
            BULK_LD(d,       (const char*)g_kh + ko, FOP, mb);
            BULK_LD(d + FOP, (const char*)g_vh + ko, FOP, mb);
        }
        if (tid < 64)
            biasp[s * 64 + tid] =
                (kpm[b * SEQ + krow0 + tid] != 0) ? 0.f : -1e30f;

        if (s == 0) { MBARRIER_WAIT_PARITY(sb + FMB, ph0); ph0 ^= 1; }
        else        { MBARRIER_WAIT_PARITY(sb + FMB + 8, ph1); ph1 ^= 1; }
        __syncthreads();

        // ---- S = Q K^T: 1 MMA per fragment ----
        float sc[8][4];
#pragma unroll
        for (int ni = 0; ni < 8; ni++)
#pragma unroll
            for (int e = 0; e < 4; e++) sc[ni][e] = 0.f;

#pragma unroll
        for (int kd = 0; kd < 4; kd++) {
            uint32_t qfh[4];
            ldsm4(qfh, sb + QOFF + a_off + kd * 32);
            uint32_t kh[4][4];
#pragma unroll
            for (int g = 0; g < 4; g++)
                ldsm4(kh[g], stg + b_off + kd * 32 + g * 16 * FSTR);
#pragma unroll
            for (int ni = 0; ni < 8; ni++) {
                const int g = ni >> 1, sel = (ni & 1) * 2;
                mma_f16(sc[ni], qfh, &kh[g][sel]);
            }
        }

        // ---- bias + causal mask ----
#pragma unroll
        for (int ni = 0; ni < 8; ni++) {
            float2 bb = *reinterpret_cast<float2*>(&biasp[s * 64 + ni * 8 + 2 * tig]);
            sc[ni][0] += bb.x; sc[ni][1] += bb.y;
            sc[ni][2] += bb.x; sc[ni][3] += bb.y;
        }
        if (krow0 + 63 > qrow0) {
            const int r0 = qrow0 + w * 16 + grp;
            const int r1 = r0 + 8;
#pragma unroll
            for (int ni = 0; ni < 8; ni++) {
                int c0 = krow0 + ni * 8 + 2 * tig;
                if (c0 > r0) sc[ni][0] = -1e30f;
                if (c0 + 1 > r0) sc[ni][1] = -1e30f;
                if (c0 > r1) sc[ni][2] = -1e30f;
                if (c0 + 1 > r1) sc[ni][3] = -1e30f;
            }
        }

        // ---- online softmax (log2 domain) ----
        float mx0 = -1e30f, mx1 = -1e30f;
#pragma unroll
        for (int ni = 0; ni < 8; ni++) {
            mx0 = fmaxf(mx0, fmaxf(sc[ni][0], sc[ni][1]));
            mx1 = fmaxf(mx1, fmaxf(sc[ni][2], sc[ni][3]));
        }
        mx0 = fmaxf(mx0, __shfl_xor_sync(0xffffffffu, mx0, 1));
        mx0 = fmaxf(mx0, __shfl_xor_sync(0xffffffffu, mx0, 2));
        mx1 = fmaxf(mx1, __shfl_xor_sync(0xffffffffu, mx1, 1));
        mx1 = fmaxf(mx1, __shfl_xor_sync(0xffffffffu, mx1, 2));
        float mn0 = fmaxf(m0, mx0), mn1 = fmaxf(m1, mx1);
        float cr0 = fexp2(m0 - mn0);
        float cr1 = fexp2(m1 - mn1);
        m0 = mn0; m1 = mn1;
#pragma unroll
        for (int ni = 0; ni < 8; ni++) {
            o[ni][0] *= cr0; o[ni][1] *= cr0;
            o[ni][2] *= cr1; o[ni][3] *= cr1;
        }
        o9[0] *= cr0; o9[1] *= cr0;
        o9[2] *= cr1; o9[3] *= cr1;

        // ---- exp/pack interleaved with PV MMAs (incl. ones column) ----
        uint32_t pa[2][4];
#pragma unroll
        for (int kc = 0; kc < 5; kc++) {
            if (kc < 4) {
                const int par = kc & 1;
#pragma unroll
                for (int j = 0; j < 2; j++) {
                    const int ni = 2 * kc + j;
                    float p0 = fexp2(sc[ni][0] - mn0);
                    float p1 = fexp2(sc[ni][1] - mn0);
                    float p2 = fexp2(sc[ni][2] - mn1);
                    float p3 = fexp2(sc[ni][3] - mn1);
                    pa[par][j * 2]     = pack_f16(p0, p1);
                    pa[par][j * 2 + 1] = pack_f16(p2, p3);
                }
            }
            if (kc > 0) {
                const int kcm = kc - 1;
                const int par = kcm & 1;
                uint32_t vh[4][4], v9[4];
#pragma unroll
                for (int g = 0; g < 4; g++)
                    ldsm4t(vh[g], stg + FOP + kcm * 16 * FSTR + t_off + g * 32);
                ldsm4t(v9, stg + FOP + kcm * 16 * FSTR + t_off + 128);
#pragma unroll
                for (int ni = 0; ni < 8; ni++) {
                    const int g = ni >> 1, sel = (ni & 1) * 2;
                    mma_f16(o[ni], pa[par], &vh[g][sel]);
                }
                mma_f16(o9, pa[par], &v9[0]);
            }
        }
        __syncthreads();
    }

    // ---- epilogue: l from ones-column (tig 0 lanes hold col 64) ----
    const int src = (lane >> 2) << 2;
    float l0 = __shfl_sync(0xffffffffu, o9[0], src);
    float l1 = __shfl_sync(0xffffffffu, o9[2], src);
    const int r0 = qrow0 + w * 16 + grp;
    const int r1 = r0 + 8;
    float f0 = (l0 > 0.f ? 1.0f / l0 : 0.f) * (float)qpm[b * SEQ + r0];
    float f1 = (l1 > 0.f ? 1.0f / l1 : 0.f) * (float)qpm[b * SEQ + r1];
    const size_t m0r = (size_t)(b * SEQ + r0);
    const size_t m1r = (size_t)(b * SEQ + r1);
#pragma unroll
    for (int ni = 0; ni < 8; ni++) {
        int col = h * HD + ni * 8 + 2 * tig;
        size_t kslab = (size_t)(col >> 5) * ((size_t)MTOT * 80) +
                       (size_t)(col & 31) * 2;
        *reinterpret_cast<uint32_t*>(g_aoh + kslab + m0r * 80) =
            pack_f16(o[ni][0] * f0, o[ni][1] * f0);
        *reinterpret_cast<uint32_t*>(g_aoh + kslab + m1r * 80) =
            pack_f16(o[ni][2] * f1, o[ni][3] * f1);
    }
}

// ---------------- launch -----------------------------------------------------
extern "C" void kernel_launch(void* const* d_in, const int* in_sizes, int n_in,
                              void* d_out, int out_size) {
    const float* q   = (const float*)d_in[0];
    const float* k   = (const float*)d_in[1];
    const float* v   = (const float*)d_in[2];
    const int*   qpm = (const int*)d_in[3];
    const int*   kpm = (const int*)d_in[4];
    const float* Wq  = (const float*)d_in[5];
    const float* Wk  = (const float*)d_in[6];
    const float* Wv  = (const float*)d_in[7];
    const float* Wo  = (const float*)d_in[8];
    float* out = (float*)d_out;

    dim3 gs((MTOT * DM) / (256 * 4), 1, 3);
    split_act_kernel<<<gs, 256>>>(q, k, v);
    split_w_kernel<<<dim3(32, 32, 4), 256>>>(Wq, Wk, Wv, Wo);

    cudaFuncSetAttribute(gemm_qkv_kernel,
                         cudaFuncAttributeMaxDynamicSharedMemorySize, GEMM_SMEM);
    cudaFuncSetAttribute(gemm_o_kernel,
                         cudaFuncAttributeMaxDynamicSharedMemorySize, GEMM_SMEM);
    gemm_qkv_kernel<<<dim3(DM / 128, MTOT / 128, 3), 256, GEMM_SMEM>>>();

    cudaFuncSetAttribute(flash_kernel,
                         cudaFuncAttributeMaxDynamicSharedMemorySize, FLASH_SMEM);
    flash_kernel<<<dim3(SEQ / 128, NB * NH), 256, FLASH_SMEM>>>(qpm, kpm);

    gemm_o_kernel<<<dim3(DM / 128, MTOT / 128), 256, GEMM_SMEM>>>(out);
}